// round 16
// baseline (speedup 1.0000x reference)
#include <cuda_runtime.h>
#include <cuda_fp16.h>
#include <math.h>
#include <float.h>
#include <stdint.h>

// Problem constants
#define BATCH   32
#define TLEN    2048
#define MROWS   (BATCH * TLEN)   // 65536
#define DIN     1024             // EPROJS = DUNITS
#define NATT    512              // ATT_DIM
#define NCH     32               // ACONV_CHANS
#define KFILT   31               // 2*15+1

#define KTOT    1056             // 1024 (enc) + 32 (conv channels)
#define NCHUNKS 33               // KTOT / 32
#define NSLICES 4                // 512 / 128 N-tiles

// ---------------- scratch (__device__ globals) ---------------------------------------
__device__ float  g_bias[BATCH * NATT];            // dec_z@W_dec + b_enc
__device__ float  g_epart[NSLICES * MROWS];        // energy partials per N-slice
__device__ __half g_Apad[(size_t)MROWS * KTOT];    // fp16 A: enc (cols 0..1023) + conv (1024..1055)
__device__ __half g_Bp[(size_t)NATT * KTOT];       // fp16 weights, B^T [n][k]

// ---------------- PTX helpers --------------------------------------------------------
__device__ __forceinline__ uint32_t smem_u32(const void* p) {
    uint32_t a;
    asm("{ .reg .u64 t; cvta.to.shared.u64 t, %1; cvt.u32.u64 %0, t; }" : "=r"(a) : "l"(p));
    return a;
}
__device__ __forceinline__ void ldmx4(uint32_t* r, uint32_t addr) {
    asm volatile("ldmatrix.sync.aligned.m8n8.x4.shared.b16 {%0,%1,%2,%3}, [%4];"
                 : "=r"(r[0]), "=r"(r[1]), "=r"(r[2]), "=r"(r[3]) : "r"(addr));
}
__device__ __forceinline__ void mma16816(float* d, const uint32_t* a, const uint32_t* b) {
    asm volatile(
        "mma.sync.aligned.m16n8k16.row.col.f32.f16.f16.f32 "
        "{%0,%1,%2,%3}, {%4,%5,%6,%7}, {%8,%9}, {%0,%1,%2,%3};"
        : "+f"(d[0]), "+f"(d[1]), "+f"(d[2]), "+f"(d[3])
        : "r"(a[0]), "r"(a[1]), "r"(a[2]), "r"(a[3]), "r"(b[0]), "r"(b[1]));
}
__device__ __forceinline__ void cp16(uint32_t sdst, const void* gsrc) {
    asm volatile("cp.async.cg.shared.global [%0], [%1], 16;"
                 :: "r"(sdst), "l"(gsrc) : "memory");
}
__device__ __forceinline__ void cp_commit() {
    asm volatile("cp.async.commit_group;" ::: "memory");
}

// ---------------- kernel A0: enc fp32 -> g_Apad fp16 (cols 0..1023) ------------------
__global__ void __launch_bounds__(256)
aconv_kernel(const float* __restrict__ enc) {
    int i = blockIdx.x * blockDim.x + threadIdx.x;   // 8 floats per thread
    int m = i >> 7;
    int g = i & 127;
    const float4* src = (const float4*)(enc + (size_t)m * DIN + g * 8);
    float4 f0 = src[0], f1 = src[1];
    __half2 h0 = __floats2half2_rn(f0.x, f0.y);
    __half2 h1 = __floats2half2_rn(f0.z, f0.w);
    __half2 h2 = __floats2half2_rn(f1.x, f1.y);
    __half2 h3 = __floats2half2_rn(f1.z, f1.w);
    uint4 v = make_uint4(*(uint32_t*)&h0, *(uint32_t*)&h1,
                         *(uint32_t*)&h2, *(uint32_t*)&h3);
    *(uint4*)(g_Apad + (size_t)m * KTOT + g * 8) = v;
}

// ---------------- kernel A: bias[b][a] = b_enc[a] + dec_z[b,:]@W_dec[:,a] ------------
__global__ void bias_kernel(const float* __restrict__ dec_z,
                            const float* __restrict__ W_dec,
                            const float* __restrict__ b_enc) {
    int b = blockIdx.x;
    int a = threadIdx.x;
    const float* dz = dec_z + b * DIN;
    float a0 = 0, a1 = 0, a2 = 0, a3 = 0;
    #pragma unroll 2
    for (int d = 0; d < DIN; d += 4) {
        a0 += dz[d + 0] * W_dec[(d + 0) * NATT + a];
        a1 += dz[d + 1] * W_dec[(d + 1) * NATT + a];
        a2 += dz[d + 2] * W_dec[(d + 2) * NATT + a];
        a3 += dz[d + 3] * W_dec[(d + 3) * NATT + a];
    }
    g_bias[b * NATT + a] = b_enc[a] + ((a0 + a1) + (a2 + a3));
}

// ---------------- kernel B: location conv -> g_Apad cols 1024..1055 (fp16) -----------
__global__ void conv_kernel(const float* __restrict__ att_prev,
                            const float* __restrict__ conv_w) {
    __shared__ float cw[NCH * KFILT];
    for (int i = threadIdx.x; i < NCH * KFILT; i += blockDim.x)
        cw[i] = conv_w[i];
    __syncthreads();

    int idx = blockIdx.x * blockDim.x + threadIdx.x;   // b*T + t
    int b = idx >> 11;
    int t = idx & (TLEN - 1);
    const float* ap = att_prev + b * TLEN;

    float win[KFILT];
    #pragma unroll
    for (int k = 0; k < KFILT; k++) {
        int tt = t + k - (KFILT / 2);
        win[k] = (tt >= 0 && tt < TLEN) ? ap[tt] : 0.0f;
    }
    __half* out = g_Apad + (size_t)idx * KTOT + DIN;
    #pragma unroll
    for (int c = 0; c < NCH; c++) {
        float s = 0.0f;
        #pragma unroll
        for (int k = 0; k < KFILT; k++)
            s += cw[c * KFILT + k] * win[k];
        out[c] = __float2half_rn(s);
    }
}

// ---------------- kernel C: weight prep -> fp16, B^T [n][k] layout -------------------
__global__ void wprep_kernel(const float* __restrict__ W_enc,
                             const float* __restrict__ W_att) {
    int n = blockIdx.x;                    // 0..511
    for (int k = threadIdx.x; k < KTOT; k += 256) {
        float w = (k < DIN) ? W_enc[(size_t)k * NATT + n]
                            : W_att[(size_t)(k - DIN) * NATT + n];
        g_Bp[(size_t)n * KTOT + k] = __float2half_rn(w);
    }
}

// ---------------- kernel D: cp.async pipelined fused energy GEMM ---------------------
// CTA tile 128m x 128n, K = 1056 in 33 chunks of 32, fp32 accumulators, 4-stage
// cp.async pipeline. Epilogue: +bias, tanh, dot W_g -> g_epart (never hits DRAM).
#define LDS_ROW 40                 // fp16 elements per smem row (80B, conflict-free)
#define STAGE_BYTES 20480          // A 10240 + B 10240
#define OFF_B  10240
#define SMEM_TOTAL (4 * STAGE_BYTES)   // 81920; epilogue aliases stage 0

__global__ void __launch_bounds__(256, 2)
energy_mma(const float* __restrict__ W_g) {
    extern __shared__ char smem[];
    const uint32_t sb = smem_u32(smem);
    const int tid  = threadIdx.x;
    const int wid  = tid >> 5;
    const int lane = tid & 31;
    const int warp_m = wid & 3;            // 4 warps over m (32-row bands)
    const int warp_n = wid >> 2;           // 2 warps over n (64-col bands)

    const int slice = blockIdx.x;          // n-tile 0..3 (fastest -> A reuse in L2)
    const int n0    = slice * 128;
    const int row0  = blockIdx.y * 128;
    const int b     = row0 >> 11;

    // per-thread invariant ldmatrix offsets (bytes)
    const uint32_t aoff0 = ((warp_m * 32 + (lane & 15)) * LDS_ROW + (lane >> 4) * 8) * 2;
    const uint32_t boff0 = ((warp_n * 64 + ((lane >> 4) & 1) * 8 + (lane & 7)) * LDS_ROW
                            + ((lane >> 3) & 1) * 8) * 2;

    // per-thread cp.async lanes: 2 segments of 16B each for A and B
    const int seg0_r  = tid >> 2;              // 0..63   (rows 0..63)
    const int seg0_kg = tid & 3;
    const int seg1_r  = seg0_r + 64;           // rows 64..127

    const __half* gA = g_Apad + (size_t)row0 * KTOT;
    const __half* gB = g_Bp   + (size_t)n0   * KTOT;

    float acc[2][8][4];
    #pragma unroll
    for (int i = 0; i < 2; i++)
        #pragma unroll
        for (int j = 0; j < 8; j++)
            #pragma unroll
            for (int q = 0; q < 4; q++) acc[i][j][q] = 0.0f;

    auto issue = [&](int c) {
        const uint32_t st = sb + (uint32_t)(c & 3) * STAGE_BYTES;
        const __half* ga = gA + c * 32;
        const __half* gb = gB + c * 32;
        cp16(st + (uint32_t)(seg0_r * LDS_ROW + seg0_kg * 8) * 2,
             ga + (size_t)seg0_r * KTOT + seg0_kg * 8);
        cp16(st + (uint32_t)(seg1_r * LDS_ROW + seg0_kg * 8) * 2,
             ga + (size_t)seg1_r * KTOT + seg0_kg * 8);
        cp16(st + OFF_B + (uint32_t)(seg0_r * LDS_ROW + seg0_kg * 8) * 2,
             gb + (size_t)seg0_r * KTOT + seg0_kg * 8);
        cp16(st + OFF_B + (uint32_t)(seg1_r * LDS_ROW + seg0_kg * 8) * 2,
             gb + (size_t)seg1_r * KTOT + seg0_kg * 8);
    };

    // prologue: 3 stages in flight
    issue(0); cp_commit();
    issue(1); cp_commit();
    issue(2); cp_commit();

    for (int c = 0; c < NCHUNKS; c++) {
        asm volatile("cp.async.wait_group 2;" ::: "memory");
        __syncthreads();                    // stage c visible; slot (c-1)&3 free

        const uint32_t sbase = sb + (uint32_t)(c & 3) * STAGE_BYTES;
        #pragma unroll
        for (int ks = 0; ks < 2; ks++) {
            uint32_t ah[2][4];
            #pragma unroll
            for (int mi = 0; mi < 2; mi++) {
                uint32_t ao = aoff0 + mi * (16 * LDS_ROW * 2) + ks * 32;
                ldmx4(ah[mi], sbase + ao);
            }
            #pragma unroll
            for (int njp = 0; njp < 4; njp++) {
                uint32_t bh[4];
                uint32_t bo = boff0 + njp * (16 * LDS_ROW * 2) + ks * 32;
                ldmx4(bh, sbase + OFF_B + bo);
                #pragma unroll
                for (int mi = 0; mi < 2; mi++) {
                    mma16816(acc[mi][2 * njp],     ah[mi], bh);
                    mma16816(acc[mi][2 * njp + 1], ah[mi], bh + 2);
                }
            }
        }

        if (c + 3 < NCHUNKS) issue(c + 3);
        cp_commit();
    }

    asm volatile("cp.async.wait_group 0;" ::: "memory");
    __syncthreads();

    // ---- epilogue: +bias, tanh, dot W_g, reduce N-slice (aliases stage 0) ----
    float* bias_s = (float*)(smem);
    float* wg_s   = (float*)(smem + 512);
    float* red    = (float*)(smem + 1024);     // red[128][8]
    if (tid < 128) {
        bias_s[tid] = g_bias[b * NATT + n0 + tid];
        wg_s[tid]   = W_g[n0 + tid];
    }
    __syncthreads();

    const int g  = lane >> 2;       // row group 0..7
    const int c4 = lane & 3;        // col group 0..3
    #pragma unroll
    for (int mi = 0; mi < 2; mi++) {
        #pragma unroll
        for (int rr = 0; rr < 2; rr++) {
            float s = 0.0f;
            #pragma unroll
            for (int j = 0; j < 8; j++) {
                int nl0 = warp_n * 64 + j * 8 + c4 * 2;
                s += tanhf(acc[mi][j][rr * 2 + 0] + bias_s[nl0])     * wg_s[nl0];
                s += tanhf(acc[mi][j][rr * 2 + 1] + bias_s[nl0 + 1]) * wg_s[nl0 + 1];
            }
            int m = warp_m * 32 + mi * 16 + rr * 8 + g;
            red[m * 8 + warp_n * 4 + c4] = s;
        }
    }
    __syncthreads();
    if (tid < 128) {
        float s = 0.0f;
        #pragma unroll
        for (int x = 0; x < 8; x++) s += red[tid * 8 + x];
        g_epart[slice * MROWS + row0 + tid] = s;
    }
}

// ---------------- kernel E: masked softmax over T per batch row ----------------------
__global__ void softmax_kernel(const int* __restrict__ lens,
                               const float* __restrict__ b_g,
                               float* __restrict__ out_w) {
    int b = blockIdx.x;
    __shared__ float es[TLEN];
    __shared__ float rbuf[256];
    const int len = lens[b];
    const float bg = b_g[0];

    float lmax = -FLT_MAX;
    for (int t = threadIdx.x; t < TLEN; t += 256) {
        int idx = b * TLEN + t;
        float e = bg + g_epart[idx] + g_epart[MROWS + idx]
                     + g_epart[2 * MROWS + idx] + g_epart[3 * MROWS + idx];
        e = (t < len) ? 2.0f * e : -INFINITY;   // SCALING=2, mask t>=len
        es[t] = e;
        lmax = fmaxf(lmax, e);
    }
    rbuf[threadIdx.x] = lmax;
    __syncthreads();
    for (int s = 128; s > 0; s >>= 1) {
        if (threadIdx.x < s)
            rbuf[threadIdx.x] = fmaxf(rbuf[threadIdx.x], rbuf[threadIdx.x + s]);
        __syncthreads();
    }
    float mx = rbuf[0];
    __syncthreads();

    float lsum = 0.0f;
    for (int t = threadIdx.x; t < TLEN; t += 256) {
        float v = expf(es[t] - mx);
        es[t] = v;
        lsum += v;
    }
    rbuf[threadIdx.x] = lsum;
    __syncthreads();
    for (int s = 128; s > 0; s >>= 1) {
        if (threadIdx.x < s)
            rbuf[threadIdx.x] += rbuf[threadIdx.x + s];
        __syncthreads();
    }
    float inv = 1.0f / rbuf[0];
    for (int t = threadIdx.x; t < TLEN; t += 256)
        out_w[b * TLEN + t] = es[t] * inv;
}

// ---------------- kernel F: weighted sum c[b,d] = sum_t w[b,t]*enc16[b,t,d] ----------
__global__ void __launch_bounds__(128)
wsum_kernel(const float* __restrict__ w, float* __restrict__ out_c) {
    int b  = blockIdx.x;
    int ds = blockIdx.y;                    // 8 slices of 128 d's
    int d  = ds * 128 + threadIdx.x;

    __shared__ float ws[TLEN];
    for (int t = threadIdx.x; t < TLEN; t += 128)
        ws[t] = w[b * TLEN + t];
    __syncthreads();

    const __half* base = g_Apad + (size_t)b * TLEN * KTOT + d;
    float a0 = 0, a1 = 0, a2 = 0, a3 = 0;
    #pragma unroll 2
    for (int t = 0; t < TLEN; t += 4) {
        a0 += __half2float(base[(size_t)(t + 0) * KTOT]) * ws[t + 0];
        a1 += __half2float(base[(size_t)(t + 1) * KTOT]) * ws[t + 1];
        a2 += __half2float(base[(size_t)(t + 2) * KTOT]) * ws[t + 2];
        a3 += __half2float(base[(size_t)(t + 3) * KTOT]) * ws[t + 3];
    }
    out_c[b * DIN + d] = (a0 + a1) + (a2 + a3);
}

// ---------------- launch -------------------------------------------------------------
extern "C" void kernel_launch(void* const* d_in, const int* in_sizes, int n_in,
                              void* d_out, int out_size) {
    const float* enc      = (const float*)d_in[0];   // (32,2048,1024)
    const int*   lens     = (const int*)  d_in[1];   // (32,)
    const float* dec_z    = (const float*)d_in[2];   // (32,1024)
    const float* att_prev = (const float*)d_in[3];   // (32,2048)
    const float* W_enc    = (const float*)d_in[4];   // (1024,512)
    const float* b_enc    = (const float*)d_in[5];   // (512,)
    const float* W_dec    = (const float*)d_in[6];   // (1024,512)
    const float* W_att    = (const float*)d_in[7];   // (32,512)
    const float* conv_w   = (const float*)d_in[8];   // (32,1,31)
    const float* W_g      = (const float*)d_in[9];   // (512,1)
    const float* b_g      = (const float*)d_in[10];  // (1,)

    float* out   = (float*)d_out;
    float* out_c = out;                  // (32,1024)
    float* out_w = out + BATCH * DIN;    // (32,2048)

    cudaFuncSetAttribute(energy_mma, cudaFuncAttributeMaxDynamicSharedMemorySize, SMEM_TOTAL);

    aconv_kernel<<<(MROWS * DIN / 8) / 256, 256>>>(enc);
    conv_kernel<<<MROWS / 256, 256>>>(att_prev, conv_w);
    wprep_kernel<<<NATT, 256>>>(W_enc, W_att);
    bias_kernel<<<BATCH, NATT>>>(dec_z, W_dec, b_enc);
    energy_mma<<<dim3(NSLICES, MROWS / 128), 256, SMEM_TOTAL>>>(W_g);
    softmax_kernel<<<BATCH, 256>>>(lens, b_g, out_w);
    wsum_kernel<<<dim3(BATCH, 8), 128>>>(out_w, out_c);
}

// round 17
// speedup vs baseline: 1.0012x; 1.0012x over previous
#include <cuda_runtime.h>
#include <cuda_fp16.h>
#include <math.h>
#include <float.h>
#include <stdint.h>

// Problem constants
#define BATCH   32
#define TLEN    2048
#define MROWS   (BATCH * TLEN)   // 65536
#define DIN     1024             // EPROJS = DUNITS
#define NATT    512              // ATT_DIM
#define NCH     32               // ACONV_CHANS
#define KFILT   31               // 2*15+1

#define KTOT    1056             // 1024 (enc) + 32 (conv channels)
#define NCHUNKS 33               // KTOT / 32
#define NSLICES 4                // 512 / 128 N-tiles

// ---------------- scratch (__device__ globals) ---------------------------------------
__device__ float  g_bias[BATCH * NATT];            // dec_z@W_dec + b_enc
__device__ float  g_epart[NSLICES * MROWS];        // energy partials per N-slice
__device__ __half g_Apad[(size_t)MROWS * KTOT];    // fp16 A: enc (cols 0..1023) + conv (1024..1055)
__device__ __half g_Bp[(size_t)NATT * KTOT];       // fp16 weights, B^T [n][k]

// ---------------- PTX helpers --------------------------------------------------------
__device__ __forceinline__ uint32_t smem_u32(const void* p) {
    uint32_t a;
    asm("{ .reg .u64 t; cvta.to.shared.u64 t, %1; cvt.u32.u64 %0, t; }" : "=r"(a) : "l"(p));
    return a;
}
__device__ __forceinline__ void ldmx4(uint32_t* r, uint32_t addr) {
    asm volatile("ldmatrix.sync.aligned.m8n8.x4.shared.b16 {%0,%1,%2,%3}, [%4];"
                 : "=r"(r[0]), "=r"(r[1]), "=r"(r[2]), "=r"(r[3]) : "r"(addr));
}
__device__ __forceinline__ void mma16816(float* d, const uint32_t* a, const uint32_t* b) {
    asm volatile(
        "mma.sync.aligned.m16n8k16.row.col.f32.f16.f16.f32 "
        "{%0,%1,%2,%3}, {%4,%5,%6,%7}, {%8,%9}, {%0,%1,%2,%3};"
        : "+f"(d[0]), "+f"(d[1]), "+f"(d[2]), "+f"(d[3])
        : "r"(a[0]), "r"(a[1]), "r"(a[2]), "r"(a[3]), "r"(b[0]), "r"(b[1]));
}
__device__ __forceinline__ void cp16(uint32_t sdst, const void* gsrc) {
    asm volatile("cp.async.cg.shared.global [%0], [%1], 16;"
                 :: "r"(sdst), "l"(gsrc) : "memory");
}
__device__ __forceinline__ void cp_commit() {
    asm volatile("cp.async.commit_group;" ::: "memory");
}

// ---------------- kernel A0: enc fp32 -> g_Apad fp16 (cols 0..1023) ------------------
__global__ void __launch_bounds__(256)
aconv_kernel(const float* __restrict__ enc) {
    int i = blockIdx.x * blockDim.x + threadIdx.x;   // 8 floats per thread
    int m = i >> 7;
    int g = i & 127;
    const float4* src = (const float4*)(enc + (size_t)m * DIN + g * 8);
    float4 f0 = src[0], f1 = src[1];
    __half2 h0 = __floats2half2_rn(f0.x, f0.y);
    __half2 h1 = __floats2half2_rn(f0.z, f0.w);
    __half2 h2 = __floats2half2_rn(f1.x, f1.y);
    __half2 h3 = __floats2half2_rn(f1.z, f1.w);
    uint4 v = make_uint4(*(uint32_t*)&h0, *(uint32_t*)&h1,
                         *(uint32_t*)&h2, *(uint32_t*)&h3);
    *(uint4*)(g_Apad + (size_t)m * KTOT + g * 8) = v;
}

// ---------------- kernel A: bias[b][a] = b_enc[a] + dec_z[b,:]@W_dec[:,a] ------------
__global__ void bias_kernel(const float* __restrict__ dec_z,
                            const float* __restrict__ W_dec,
                            const float* __restrict__ b_enc) {
    int b = blockIdx.x;
    int a = threadIdx.x;
    const float* dz = dec_z + b * DIN;
    float a0 = 0, a1 = 0, a2 = 0, a3 = 0;
    #pragma unroll 2
    for (int d = 0; d < DIN; d += 4) {
        a0 += dz[d + 0] * W_dec[(d + 0) * NATT + a];
        a1 += dz[d + 1] * W_dec[(d + 1) * NATT + a];
        a2 += dz[d + 2] * W_dec[(d + 2) * NATT + a];
        a3 += dz[d + 3] * W_dec[(d + 3) * NATT + a];
    }
    g_bias[b * NATT + a] = b_enc[a] + ((a0 + a1) + (a2 + a3));
}

// ---------------- kernel B: location conv -> g_Apad cols 1024..1055 (fp16) -----------
__global__ void conv_kernel(const float* __restrict__ att_prev,
                            const float* __restrict__ conv_w) {
    __shared__ float cw[NCH * KFILT];
    for (int i = threadIdx.x; i < NCH * KFILT; i += blockDim.x)
        cw[i] = conv_w[i];
    __syncthreads();

    int idx = blockIdx.x * blockDim.x + threadIdx.x;   // b*T + t
    int b = idx >> 11;
    int t = idx & (TLEN - 1);
    const float* ap = att_prev + b * TLEN;

    float win[KFILT];
    #pragma unroll
    for (int k = 0; k < KFILT; k++) {
        int tt = t + k - (KFILT / 2);
        win[k] = (tt >= 0 && tt < TLEN) ? ap[tt] : 0.0f;
    }
    __half* out = g_Apad + (size_t)idx * KTOT + DIN;
    #pragma unroll
    for (int c = 0; c < NCH; c++) {
        float s = 0.0f;
        #pragma unroll
        for (int k = 0; k < KFILT; k++)
            s += cw[c * KFILT + k] * win[k];
        out[c] = __float2half_rn(s);
    }
}

// ---------------- kernel C: weight prep -> fp16, B^T [n][k] layout -------------------
__global__ void wprep_kernel(const float* __restrict__ W_enc,
                             const float* __restrict__ W_att) {
    int n = blockIdx.x;                    // 0..511
    for (int k = threadIdx.x; k < KTOT; k += 256) {
        float w = (k < DIN) ? W_enc[(size_t)k * NATT + n]
                            : W_att[(size_t)(k - DIN) * NATT + n];
        g_Bp[(size_t)n * KTOT + k] = __float2half_rn(w);
    }
}

// ---------------- kernel D: cp.async pipelined fused energy GEMM ---------------------
// CTA tile 128m x 128n, K = 1056 in 33 chunks of 32, fp32 accumulators, 4-stage
// cp.async pipeline. Epilogue: +bias, tanh, dot W_g -> g_epart (never hits DRAM).
#define LDS_ROW 40                 // fp16 elements per smem row (80B, conflict-free)
#define STAGE_BYTES 20480          // A 10240 + B 10240
#define OFF_B  10240
#define SMEM_TOTAL (4 * STAGE_BYTES)   // 81920; epilogue aliases stage 0

__global__ void __launch_bounds__(256, 2)
energy_mma(const float* __restrict__ W_g) {
    extern __shared__ char smem[];
    const uint32_t sb = smem_u32(smem);
    const int tid  = threadIdx.x;
    const int wid  = tid >> 5;
    const int lane = tid & 31;
    const int warp_m = wid & 3;            // 4 warps over m (32-row bands)
    const int warp_n = wid >> 2;           // 2 warps over n (64-col bands)

    const int slice = blockIdx.x;          // n-tile 0..3 (fastest -> A reuse in L2)
    const int n0    = slice * 128;
    const int row0  = blockIdx.y * 128;
    const int b     = row0 >> 11;

    // per-thread invariant ldmatrix offsets (bytes)
    const uint32_t aoff0 = ((warp_m * 32 + (lane & 15)) * LDS_ROW + (lane >> 4) * 8) * 2;
    const uint32_t boff0 = ((warp_n * 64 + ((lane >> 4) & 1) * 8 + (lane & 7)) * LDS_ROW
                            + ((lane >> 3) & 1) * 8) * 2;

    // per-thread cp.async lanes: 2 segments of 16B each for A and B
    const int seg0_r  = tid >> 2;              // 0..63   (rows 0..63)
    const int seg0_kg = tid & 3;
    const int seg1_r  = seg0_r + 64;           // rows 64..127

    const __half* gA = g_Apad + (size_t)row0 * KTOT;
    const __half* gB = g_Bp   + (size_t)n0   * KTOT;

    float acc[2][8][4];
    #pragma unroll
    for (int i = 0; i < 2; i++)
        #pragma unroll
        for (int j = 0; j < 8; j++)
            #pragma unroll
            for (int q = 0; q < 4; q++) acc[i][j][q] = 0.0f;

    auto issue = [&](int c) {
        const uint32_t st = sb + (uint32_t)(c & 3) * STAGE_BYTES;
        const __half* ga = gA + c * 32;
        const __half* gb = gB + c * 32;
        cp16(st + (uint32_t)(seg0_r * LDS_ROW + seg0_kg * 8) * 2,
             ga + (size_t)seg0_r * KTOT + seg0_kg * 8);
        cp16(st + (uint32_t)(seg1_r * LDS_ROW + seg0_kg * 8) * 2,
             ga + (size_t)seg1_r * KTOT + seg0_kg * 8);
        cp16(st + OFF_B + (uint32_t)(seg0_r * LDS_ROW + seg0_kg * 8) * 2,
             gb + (size_t)seg0_r * KTOT + seg0_kg * 8);
        cp16(st + OFF_B + (uint32_t)(seg1_r * LDS_ROW + seg0_kg * 8) * 2,
             gb + (size_t)seg1_r * KTOT + seg0_kg * 8);
    };

    // prologue: 3 stages in flight
    issue(0); cp_commit();
    issue(1); cp_commit();
    issue(2); cp_commit();

    for (int c = 0; c < NCHUNKS; c++) {
        asm volatile("cp.async.wait_group 2;" ::: "memory");
        __syncthreads();                    // stage c visible; slot (c-1)&3 free

        const uint32_t sbase = sb + (uint32_t)(c & 3) * STAGE_BYTES;
        #pragma unroll
        for (int ks = 0; ks < 2; ks++) {
            uint32_t ah[2][4];
            #pragma unroll
            for (int mi = 0; mi < 2; mi++) {
                uint32_t ao = aoff0 + mi * (16 * LDS_ROW * 2) + ks * 32;
                ldmx4(ah[mi], sbase + ao);
            }
            #pragma unroll
            for (int njp = 0; njp < 4; njp++) {
                uint32_t bh[4];
                uint32_t bo = boff0 + njp * (16 * LDS_ROW * 2) + ks * 32;
                ldmx4(bh, sbase + OFF_B + bo);
                #pragma unroll
                for (int mi = 0; mi < 2; mi++) {
                    mma16816(acc[mi][2 * njp],     ah[mi], bh);
                    mma16816(acc[mi][2 * njp + 1], ah[mi], bh + 2);
                }
            }
        }

        if (c + 3 < NCHUNKS) issue(c + 3);
        cp_commit();
    }

    asm volatile("cp.async.wait_group 0;" ::: "memory");
    __syncthreads();

    // ---- epilogue: +bias, tanh, dot W_g, reduce N-slice (aliases stage 0) ----
    float* bias_s = (float*)(smem);
    float* wg_s   = (float*)(smem + 512);
    float* red    = (float*)(smem + 1024);     // red[128][8]
    if (tid < 128) {
        bias_s[tid] = g_bias[b * NATT + n0 + tid];
        wg_s[tid]   = W_g[n0 + tid];
    }
    __syncthreads();

    const int g  = lane >> 2;       // row group 0..7
    const int c4 = lane & 3;        // col group 0..3
    #pragma unroll
    for (int mi = 0; mi < 2; mi++) {
        #pragma unroll
        for (int rr = 0; rr < 2; rr++) {
            float s = 0.0f;
            #pragma unroll
            for (int j = 0; j < 8; j++) {
                int nl0 = warp_n * 64 + j * 8 + c4 * 2;
                s += tanhf(acc[mi][j][rr * 2 + 0] + bias_s[nl0])     * wg_s[nl0];
                s += tanhf(acc[mi][j][rr * 2 + 1] + bias_s[nl0 + 1]) * wg_s[nl0 + 1];
            }
            int m = warp_m * 32 + mi * 16 + rr * 8 + g;
            red[m * 8 + warp_n * 4 + c4] = s;
        }
    }
    __syncthreads();
    if (tid < 128) {
        float s = 0.0f;
        #pragma unroll
        for (int x = 0; x < 8; x++) s += red[tid * 8 + x];
        g_epart[slice * MROWS + row0 + tid] = s;
    }
}

// ---------------- kernel E: masked softmax over T per batch row ----------------------
__global__ void softmax_kernel(const int* __restrict__ lens,
                               const float* __restrict__ b_g,
                               float* __restrict__ out_w) {
    int b = blockIdx.x;
    __shared__ float es[TLEN];
    __shared__ float rbuf[256];
    const int len = lens[b];
    const float bg = b_g[0];

    float lmax = -FLT_MAX;
    for (int t = threadIdx.x; t < TLEN; t += 256) {
        int idx = b * TLEN + t;
        float e = bg + g_epart[idx] + g_epart[MROWS + idx]
                     + g_epart[2 * MROWS + idx] + g_epart[3 * MROWS + idx];
        e = (t < len) ? 2.0f * e : -INFINITY;   // SCALING=2, mask t>=len
        es[t] = e;
        lmax = fmaxf(lmax, e);
    }
    rbuf[threadIdx.x] = lmax;
    __syncthreads();
    for (int s = 128; s > 0; s >>= 1) {
        if (threadIdx.x < s)
            rbuf[threadIdx.x] = fmaxf(rbuf[threadIdx.x], rbuf[threadIdx.x + s]);
        __syncthreads();
    }
    float mx = rbuf[0];
    __syncthreads();

    float lsum = 0.0f;
    for (int t = threadIdx.x; t < TLEN; t += 256) {
        float v = expf(es[t] - mx);
        es[t] = v;
        lsum += v;
    }
    rbuf[threadIdx.x] = lsum;
    __syncthreads();
    for (int s = 128; s > 0; s >>= 1) {
        if (threadIdx.x < s)
            rbuf[threadIdx.x] += rbuf[threadIdx.x + s];
        __syncthreads();
    }
    float inv = 1.0f / rbuf[0];
    for (int t = threadIdx.x; t < TLEN; t += 256)
        out_w[b * TLEN + t] = es[t] * inv;
}

// ---------------- kernel F: weighted sum c[b,d] = sum_t w[b,t]*enc16[b,t,d] ----------
__global__ void __launch_bounds__(128)
wsum_kernel(const float* __restrict__ w, float* __restrict__ out_c) {
    int b  = blockIdx.x;
    int ds = blockIdx.y;                    // 8 slices of 128 d's
    int d  = ds * 128 + threadIdx.x;

    __shared__ float ws[TLEN];
    for (int t = threadIdx.x; t < TLEN; t += 128)
        ws[t] = w[b * TLEN + t];
    __syncthreads();

    const __half* base = g_Apad + (size_t)b * TLEN * KTOT + d;
    float a0 = 0, a1 = 0, a2 = 0, a3 = 0;
    #pragma unroll 2
    for (int t = 0; t < TLEN; t += 4) {
        a0 += __half2float(base[(size_t)(t + 0) * KTOT]) * ws[t + 0];
        a1 += __half2float(base[(size_t)(t + 1) * KTOT]) * ws[t + 1];
        a2 += __half2float(base[(size_t)(t + 2) * KTOT]) * ws[t + 2];
        a3 += __half2float(base[(size_t)(t + 3) * KTOT]) * ws[t + 3];
    }
    out_c[b * DIN + d] = (a0 + a1) + (a2 + a3);
}

// ---------------- launch -------------------------------------------------------------
extern "C" void kernel_launch(void* const* d_in, const int* in_sizes, int n_in,
                              void* d_out, int out_size) {
    const float* enc      = (const float*)d_in[0];   // (32,2048,1024)
    const int*   lens     = (const int*)  d_in[1];   // (32,)
    const float* dec_z    = (const float*)d_in[2];   // (32,1024)
    const float* att_prev = (const float*)d_in[3];   // (32,2048)
    const float* W_enc    = (const float*)d_in[4];   // (1024,512)
    const float* b_enc    = (const float*)d_in[5];   // (512,)
    const float* W_dec    = (const float*)d_in[6];   // (1024,512)
    const float* W_att    = (const float*)d_in[7];   // (32,512)
    const float* conv_w   = (const float*)d_in[8];   // (32,1,31)
    const float* W_g      = (const float*)d_in[9];   // (512,1)
    const float* b_g      = (const float*)d_in[10];  // (1,)

    float* out   = (float*)d_out;
    float* out_c = out;                  // (32,1024)
    float* out_w = out + BATCH * DIN;    // (32,2048)

    cudaFuncSetAttribute(energy_mma, cudaFuncAttributeMaxDynamicSharedMemorySize, SMEM_TOTAL);

    aconv_kernel<<<(MROWS * DIN / 8) / 256, 256>>>(enc);
    conv_kernel<<<MROWS / 256, 256>>>(att_prev, conv_w);
    wprep_kernel<<<NATT, 256>>>(W_enc, W_att);
    bias_kernel<<<BATCH, NATT>>>(dec_z, W_dec, b_enc);
    energy_mma<<<dim3(NSLICES, MROWS / 128), 256, SMEM_TOTAL>>>(W_g);
    softmax_kernel<<<BATCH, 256>>>(lens, b_g, out_w);
    wsum_kernel<<<dim3(BATCH, 8), 128>>>(out_w, out_c);
}